// round 15
// baseline (speedup 1.0000x reference)
#include <cuda_runtime.h>
#include <cuda_bf16.h>
#include <cuda_fp16.h>
#include <math.h>
#include <stdint.h>

#define NN 10000
#define NPAD 10112        // 79 * 128
#define NE 100000
#define NEP 110000        // edges + self-loops
#define DD 768
#define NEG_SLOPE 0.2f

// ---------------- scratch (device globals; no allocation allowed) ----------------
__device__ __half g_h[NN * DD];        // GEMM output, fp16
__device__ float g_as1[NN];
__device__ float g_ad1[NN];
__device__ float g_as2[NN];
__device__ float g_ad2[NN];
__device__ int   g_src[NE];
__device__ int   g_dst[NE];
__device__ int   g_deg[NN];            // real-edge in-degree (self-loop added in scan)
__device__ int   g_rowstart[NN + 1];
__device__ int   g_cursor[NN];
__device__ int   g_csr_src[NEP];
__device__ __half g_af16[NPAD * DD];   // A in fp16
__device__ __half g_b16a[DD * DD];     // W1^T fp16 [n][k]
__device__ __half g_b16b[DD * DD];     // W2^T fp16 [n][k]

// ================= helpers =================
__device__ __forceinline__ uint32_t smem_u32(const void* p) {
    uint32_t a;
    asm("{ .reg .u64 t; cvta.to.shared.u64 t, %1; cvt.u32.u64 %0, t; }" : "=r"(a) : "l"(p));
    return a;
}
__device__ __forceinline__ uint32_t sw64_(uint32_t off) { return off ^ ((off >> 3) & 0x30); }

__device__ __forceinline__ void ldsm_x4(uint32_t* r, uint32_t addr) {
    asm volatile("ldmatrix.sync.aligned.m8n8.x4.shared.b16 {%0,%1,%2,%3}, [%4];"
        : "=r"(r[0]), "=r"(r[1]), "=r"(r[2]), "=r"(r[3]) : "r"(addr));
}
__device__ __forceinline__ void mma_f16(float* c, const uint32_t* a, const uint32_t* b) {
    asm volatile("mma.sync.aligned.m16n8k16.row.col.f32.f16.f16.f32 "
        "{%0,%1,%2,%3}, {%4,%5,%6,%7}, {%8,%9}, {%0,%1,%2,%3};"
        : "+f"(c[0]), "+f"(c[1]), "+f"(c[2]), "+f"(c[3])
        : "r"(a[0]), "r"(a[1]), "r"(a[2]), "r"(a[3]), "r"(b[0]), "r"(b[1]));
}

// ---------------- clear (must precede prep's degree atomics) ----------------
__global__ void clear_kernel() {
    int i = blockIdx.x * blockDim.x + threadIdx.x;
    if (i < NN) {
        g_deg[i] = 0; g_cursor[i] = 0;
        g_as1[i] = 0.f; g_ad1[i] = 0.f;
        g_as2[i] = 0.f; g_ad2[i] = 0.f;
    }
}

// ---------------- fused prep: W1^T, W2^T, A->fp16, edge convert + degree ----------------
#define PREP_WT   576
#define PREP_A    432
#define PREP_EDGE 98
#define PREP_GRID (2 * PREP_WT + PREP_A + PREP_EDGE)   // 1682

__global__ __launch_bounds__(256) void prep_kernel(
    const float* __restrict__ W1, const float* __restrict__ W2,
    const float* __restrict__ x, const int* __restrict__ eraw)
{
    __shared__ float t[32][33];
    int b = blockIdx.x, tid = threadIdx.x;

    if (b < 2 * PREP_WT) {                     // ---- W transpose ----
        const float* W = (b < PREP_WT) ? W1 : W2;
        __half* Bt = (b < PREP_WT) ? g_b16a : g_b16b;
        int i = (b < PREP_WT) ? b : b - PREP_WT;
        int bx = (i % 24) * 32;                // n block
        int by = (i / 24) * 32;                // k block
        int tx = tid & 31;
        int ty = tid >> 5;
        #pragma unroll
        for (int j = 0; j < 32; j += 8)
            t[ty + j][tx] = W[(size_t)(by + ty + j) * DD + bx + tx];
        __syncthreads();
        #pragma unroll
        for (int j = 0; j < 32; j += 8)
            Bt[(size_t)(bx + ty + j) * DD + by + tx] = __float2half(t[tx][ty + j]);
    } else if (b < 2 * PREP_WT + PREP_A) {     // ---- A convert (float4 -> half2x2) ----
        const float4* x4 = (const float4*)x;
        uint2* a4 = (uint2*)g_af16;
        const int n4 = NN * DD / 4;
        const int p4 = NPAD * DD / 4;
        int idx = (b - 2 * PREP_WT) * 256 + tid;
        int stride = PREP_A * 256;
        for (int i = idx; i < p4; i += stride) {
            uint2 o;
            if (i < n4) {
                float4 v = x4[i];
                __half2 lo = __floats2half2_rn(v.x, v.y);
                __half2 hi = __floats2half2_rn(v.z, v.w);
                o.x = *(uint32_t*)&lo;
                o.y = *(uint32_t*)&hi;
            } else {
                o.x = 0u; o.y = 0u;
            }
            a4[i] = o;
        }
    } else {                                   // ---- edge convert + degree ----
        bool is64 = true;
        #pragma unroll
        for (int i = 1; i < 129; i += 2)
            if (eraw[i] != 0) is64 = false;
        int idx = (b - 2 * PREP_WT - PREP_A) * 256 + tid;
        int stride = PREP_EDGE * 256;
        for (int e = idx; e < 2 * NE; e += stride) {
            int v = is64 ? eraw[2 * e] : eraw[e];
            if (e < NE) g_src[e] = v;
            else { g_dst[e - NE] = v; atomicAdd(&g_deg[v], 1); }
        }
    }
}

// ---------------- CSR: scan (+1 self-loop per node) then scatter ----------------
__global__ __launch_bounds__(1024) void scan_kernel() {
    __shared__ int wsum[32];
    __shared__ int carry_s;
    int tid = threadIdx.x, lane = tid & 31, w = tid >> 5;
    if (tid == 0) { carry_s = 0; g_rowstart[0] = 0; }
    __syncthreads();
    for (int r = 0; r < 10; r++) {
        int i = r * 1024 + tid;
        int v = (i < NN) ? (g_deg[i] + 1) : 0;    // +1 = self-loop
        int ss = v;
        #pragma unroll
        for (int o = 1; o < 32; o <<= 1) {
            int tt = __shfl_up_sync(0xffffffffu, ss, o);
            if (lane >= o) ss += tt;
        }
        if (lane == 31) wsum[w] = ss;
        __syncthreads();
        if (w == 0) {
            int xx = wsum[lane];
            #pragma unroll
            for (int o = 1; o < 32; o <<= 1) {
                int tt = __shfl_up_sync(0xffffffffu, xx, o);
                if (lane >= o) xx += tt;
            }
            wsum[lane] = xx;
        }
        __syncthreads();
        int incl = ss + (w > 0 ? wsum[w - 1] : 0) + carry_s;
        if (i < NN) g_rowstart[i + 1] = incl;
        int total = carry_s + wsum[31];
        __syncthreads();
        if (tid == 0) carry_s = total;
        __syncthreads();
    }
}

__global__ void scatter_kernel() {
    int idx = blockIdx.x * blockDim.x + threadIdx.x;
    int stride = gridDim.x * blockDim.x;
    for (int e = idx; e < NE + NN; e += stride) {
        if (e < NE) {
            int s = g_src[e], d = g_dst[e];
            int pos = g_rowstart[d] + atomicAdd(&g_cursor[d], 1);
            g_csr_src[pos] = s;
        } else {
            int nd = e - NE;                       // self-loop at segment end
            g_csr_src[g_rowstart[nd + 1] - 1] = nd;
        }
    }
}

// ---------------- mma.sync fp16 GEMM + fused attn dots ----------------
#define BM 128
#define BN 128
#define BK 32
#define KCH (DD / BK)            // 24
#define TILE_B 8192              // 128 rows * 64 B
#define STAGE_B (2 * TILE_B)     // 16384
#define NSTAGE 4
#define GEMM_SMEM (NSTAGE * STAGE_B)  // 65536

__device__ __forceinline__ void gemm_issue_loads(
    uint32_t tiles_base, int buf, int kc, int tid, int row0, int col0,
    const __half* __restrict__ A, const __half* __restrict__ B)
{
    uint32_t base = tiles_base + (uint32_t)buf * STAGE_B;
    #pragma unroll
    for (int i = tid; i < 1024; i += 256) {
        int t = i >> 9;
        int j = i & 511;
        int r = j >> 2;
        int c16 = j & 3;
        const __half* src = (t == 0) ? A : B;
        int rowbase = (t == 0) ? row0 : col0;
        const void* g = src + (size_t)(rowbase + r) * DD + kc * BK + c16 * 8;
        uint32_t d = base + (uint32_t)t * TILE_B + sw64_((uint32_t)(r * 64 + c16 * 16));
        asm volatile("cp.async.cg.shared.global [%0], [%1], 16;\n" :: "r"(d), "l"(g) : "memory");
    }
    asm volatile("cp.async.commit_group;\n" ::: "memory");
}

__global__ __launch_bounds__(256, 2)
void gemm_f16_kernel(const __half* __restrict__ A,
                     const __half* __restrict__ B,
                     __half* __restrict__ C, int M,
                     const float* __restrict__ atts,
                     const float* __restrict__ attd,
                     float* __restrict__ as_, float* __restrict__ ad_)
{
    extern __shared__ char smem[];
    uint32_t sb = smem_u32(smem);
    int tid = threadIdx.x, wid = tid >> 5, lane = tid & 31;
    int row0 = blockIdx.y * BM;
    int col0 = blockIdx.x * BN;
    int warpM = wid & 3;
    int warpN = wid >> 2;

    float acc[2][8][4];
    #pragma unroll
    for (int mt = 0; mt < 2; mt++)
        #pragma unroll
        for (int nt = 0; nt < 8; nt++)
            #pragma unroll
            for (int q = 0; q < 4; q++) acc[mt][nt][q] = 0.f;

    int a_row_l = (lane & 7) + (((lane >> 3) & 1) << 3);
    int a_kb_l  = (lane >> 4) << 4;
    int b_row_l = (lane & 7) + ((lane >> 4) << 3);
    int b_kb_l  = ((lane >> 3) & 1) << 4;

    gemm_issue_loads(sb, 0, 0, tid, row0, col0, A, B);
    gemm_issue_loads(sb, 1, 1, tid, row0, col0, A, B);
    gemm_issue_loads(sb, 2, 2, tid, row0, col0, A, B);

    for (int c = 0; c < KCH; c++) {
        int rem = KCH - 1 - c;
        if (rem >= 2)      { asm volatile("cp.async.wait_group 2;\n" ::: "memory"); }
        else if (rem == 1) { asm volatile("cp.async.wait_group 1;\n" ::: "memory"); }
        else               { asm volatile("cp.async.wait_group 0;\n" ::: "memory"); }
        __syncthreads();
        if (c + 3 < KCH)
            gemm_issue_loads(sb, (c + 3) % NSTAGE, c + 3, tid, row0, col0, A, B);

        uint32_t sbase = sb + (uint32_t)(c % NSTAGE) * STAGE_B;
        uint32_t sA = sbase;
        uint32_t sB = sbase + TILE_B;

        #pragma unroll
        for (int ks = 0; ks < 2; ks++) {
            int kb = ks * 32;
            uint32_t ah[2][4];
            #pragma unroll
            for (int mt = 0; mt < 2; mt++) {
                int row = warpM * 32 + mt * 16 + a_row_l;
                uint32_t off = sw64_((uint32_t)(row * 64 + kb + a_kb_l));
                ldsm_x4(ah[mt], sA + off);
            }
            #pragma unroll
            for (int np = 0; np < 4; np++) {
                uint32_t bf[4];
                int nrow = warpN * 64 + np * 16 + b_row_l;
                uint32_t off = sw64_((uint32_t)(nrow * 64 + kb + b_kb_l));
                ldsm_x4(bf, sB + off);
                #pragma unroll
                for (int mt = 0; mt < 2; mt++) {
                    mma_f16(acc[mt][2 * np],     ah[mt], &bf[0]);
                    mma_f16(acc[mt][2 * np + 1], ah[mt], &bf[2]);
                }
            }
        }
    }

    int colb = col0 + warpN * 64 + (lane & 3) * 2;
    int rowb = row0 + warpM * 32 + (lane >> 2);

    // ---- fused attention dots (fp32 accumulators) ----
    {
        float ps[2][2] = {{0.f,0.f},{0.f,0.f}};
        float pd[2][2] = {{0.f,0.f},{0.f,0.f}};
        #pragma unroll
        for (int nt = 0; nt < 8; nt++) {
            int col = colb + nt * 8;
            float s0 = atts[col], s1 = atts[col + 1];
            float d0 = attd[col], d1 = attd[col + 1];
            #pragma unroll
            for (int mt = 0; mt < 2; mt++) {
                ps[mt][0] += acc[mt][nt][0] * s0 + acc[mt][nt][1] * s1;
                pd[mt][0] += acc[mt][nt][0] * d0 + acc[mt][nt][1] * d1;
                ps[mt][1] += acc[mt][nt][2] * s0 + acc[mt][nt][3] * s1;
                pd[mt][1] += acc[mt][nt][2] * d0 + acc[mt][nt][3] * d1;
            }
        }
        #pragma unroll
        for (int mt = 0; mt < 2; mt++)
            #pragma unroll
            for (int hf = 0; hf < 2; hf++) {
                #pragma unroll
                for (int o = 1; o < 4; o <<= 1) {
                    ps[mt][hf] += __shfl_xor_sync(0xffffffffu, ps[mt][hf], o);
                    pd[mt][hf] += __shfl_xor_sync(0xffffffffu, pd[mt][hf], o);
                }
            }
        if ((lane & 3) == 0) {
            #pragma unroll
            for (int mt = 0; mt < 2; mt++)
                #pragma unroll
                for (int hf = 0; hf < 2; hf++) {
                    int row = rowb + mt * 16 + hf * 8;
                    if (row < M) {
                        atomicAdd(&as_[row], ps[mt][hf]);
                        atomicAdd(&ad_[row], pd[mt][hf]);
                    }
                }
        }
    }

    // ---- store C as fp16 ----
    #pragma unroll
    for (int mt = 0; mt < 2; mt++) {
        int r0 = rowb + mt * 16;
        int r1 = r0 + 8;
        #pragma unroll
        for (int nt = 0; nt < 8; nt++) {
            int col = colb + nt * 8;
            if (r0 < M) *(__half2*)(C + (size_t)r0 * DD + col) =
                __floats2half2_rn(acc[mt][nt][0], acc[mt][nt][1]);
            if (r1 < M) *(__half2*)(C + (size_t)r1 * DD + col) =
                __floats2half2_rn(acc[mt][nt][2], acc[mt][nt][3]);
        }
    }
}

// ---------------- segment softmax + weighted aggregate ----------------
#define AGG_T 384
__global__ __launch_bounds__(AGG_T) void aggregate_kernel(
    const __half* __restrict__ h, const float* __restrict__ bias,
    const float* __restrict__ as_, const float* __restrict__ ad_,
    float* __restrict__ out, int mode)
{
    __shared__ float sh_alpha[AGG_T];
    __shared__ int   sh_src[AGG_T];
    __shared__ float red[12];
    __shared__ float s_b;

    int n = blockIdx.x, tid = threadIdx.x;
    int lane = tid & 31, w = tid >> 5;
    int rs = g_rowstart[n], re = g_rowstart[n + 1];
    float adn = ad_[n];

    float2 acc = make_float2(0.f, 0.f);
    float total = 0.f;

    for (int base = rs; base < re; base += AGG_T) {
        int cnt = min(AGG_T, re - base);
        float ex = 0.f; int s = 0;
        if (tid < cnt) {
            s = g_csr_src[base + tid];
            float t = as_[s] + adn;
            t = (t > 0.f) ? t : NEG_SLOPE * t;
            ex = __expf(t);
        }
        float v = ex;
        #pragma unroll
        for (int o = 16; o > 0; o >>= 1)
            v += __shfl_xor_sync(0xffffffffu, v, o);
        if (lane == 0) red[w] = v;
        if (tid < cnt) { sh_alpha[tid] = ex; sh_src[tid] = s; }
        __syncthreads();
        if (tid == 0) {
            float ss = 0.f;
            #pragma unroll
            for (int q = 0; q < 12; q++) ss += red[q];
            s_b = ss;
        }
        __syncthreads();
        total += s_b;

        #pragma unroll 4
        for (int j = 0; j < cnt; j++) {
            float a = sh_alpha[j];
            const __half2* hr = (const __half2*)(h + (size_t)sh_src[j] * DD);
            float2 f = __half22float2(hr[tid]);
            acc.x = fmaf(a, f.x, acc.x);
            acc.y = fmaf(a, f.y, acc.y);
        }
        __syncthreads();
    }

    float inv = 1.f / total;
    int c0 = 2 * tid;
    float2 bv = *(const float2*)(bias + c0);
    float o0 = acc.x * inv + bv.x;
    float o1 = acc.y * inv + bv.y;
    if (mode == 1) {
        o0 = fmaxf(o0, 0.f); o1 = fmaxf(o1, 0.f);
        *(__half2*)(&g_af16[(size_t)n * DD + c0]) = __floats2half2_rn(o0, o1);
    } else {
        *(float2*)(out + (size_t)n * DD + c0) = make_float2(o0, o1);
    }
}

// ---------------- launch ----------------
extern "C" void kernel_launch(void* const* d_in, const int* in_sizes, int n_in,
                              void* d_out, int out_size) {
    const float* x   = (const float*)d_in[0];
    const int*   er  = (const int*)d_in[1];
    const float* W1  = (const float*)d_in[2];
    const float* as1 = (const float*)d_in[3];
    const float* ad1 = (const float*)d_in[4];
    const float* b1  = (const float*)d_in[5];
    const float* W2  = (const float*)d_in[6];
    const float* as2 = (const float*)d_in[7];
    const float* ad2 = (const float*)d_in[8];
    const float* b2  = (const float*)d_in[9];
    float* out = (float*)d_out;

    void *p_h, *p_a, *p_ba, *p_bb, *p_s1, *p_d1, *p_s2, *p_d2;
    cudaGetSymbolAddress(&p_h, g_h);
    cudaGetSymbolAddress(&p_a, g_af16);
    cudaGetSymbolAddress(&p_ba, g_b16a);
    cudaGetSymbolAddress(&p_bb, g_b16b);
    cudaGetSymbolAddress(&p_s1, g_as1);
    cudaGetSymbolAddress(&p_d1, g_ad1);
    cudaGetSymbolAddress(&p_s2, g_as2);
    cudaGetSymbolAddress(&p_d2, g_ad2);
    __half* h = (__half*)p_h;
    const __half* a16 = (const __half*)p_a;

    cudaFuncSetAttribute(gemm_f16_kernel,
                         cudaFuncAttributeMaxDynamicSharedMemorySize, GEMM_SMEM);

    // side stream + fork/join events (created once; no device memory involved)
    static cudaStream_t s_csr = nullptr;
    static cudaEvent_t ev_prep = nullptr, ev_csr = nullptr;
    if (s_csr == nullptr) {
        cudaStreamCreateWithFlags(&s_csr, cudaStreamNonBlocking);
        cudaEventCreateWithFlags(&ev_prep, cudaEventDisableTiming);
        cudaEventCreateWithFlags(&ev_csr, cudaEventDisableTiming);
    }

    dim3 ggrid(DD / BN, NPAD / BM);          // (6, 79)

    // main: clear -> prep -> gemm1 -> (join csr) agg1 -> gemm2 -> agg2
    // csr : (fork after prep) scan -> scatter   (hides under gemm1)
    clear_kernel<<<(NN + 255) / 256, 256>>>();
    prep_kernel<<<PREP_GRID, 256>>>(W1, W2, x, er);
    cudaEventRecord(ev_prep, 0);
    cudaStreamWaitEvent(s_csr, ev_prep, 0);
    scan_kernel<<<1, 1024, 0, s_csr>>>();
    scatter_kernel<<<432, 256, 0, s_csr>>>();
    cudaEventRecord(ev_csr, s_csr);

    gemm_f16_kernel<<<ggrid, 256, GEMM_SMEM>>>(a16, (const __half*)p_ba,
        h, NN, as1, ad1, (float*)p_s1, (float*)p_d1);

    cudaStreamWaitEvent(0, ev_csr, 0);
    aggregate_kernel<<<NN, AGG_T>>>(h, b1, (const float*)p_s1,
        (const float*)p_d1, nullptr, 1);
    gemm_f16_kernel<<<ggrid, 256, GEMM_SMEM>>>(a16, (const __half*)p_bb,
        h, NN, as2, ad2, (float*)p_s2, (float*)p_d2);
    aggregate_kernel<<<NN, AGG_T>>>(h, b2, (const float*)p_s2,
        (const float*)p_d2, out, 0);
}

// round 16
// speedup vs baseline: 1.4843x; 1.4843x over previous
#include <cuda_runtime.h>
#include <cuda_bf16.h>
#include <cuda_fp16.h>
#include <math.h>
#include <stdint.h>

#define NN 10000
#define NPAD 10112        // 79 * 128
#define NE 100000
#define NEP 110000        // edges + self-loops
#define DD 768
#define NEG_SLOPE 0.2f

// ---------------- scratch (device globals; no allocation allowed) ----------------
__device__ __half g_h[NN * DD];        // GEMM output, fp16
__device__ float g_as1[NN];
__device__ float g_ad1[NN];
__device__ float g_as2[NN];
__device__ float g_ad2[NN];
__device__ int   g_src[NE];
__device__ int   g_dst[NE];
__device__ int   g_deg[NN];            // real-edge in-degree (self-loop added in scan)
__device__ int   g_rowstart[NN + 1];
__device__ int   g_cursor[NN];
__device__ int   g_csr_src[NEP];
__device__ __half g_af16[NPAD * DD];   // A in fp16
__device__ __half g_b16a[DD * DD];     // W1^T fp16 [n][k]
__device__ __half g_b16b[DD * DD];     // W2^T fp16 [n][k]

// ================= helpers =================
__device__ __forceinline__ uint32_t smem_u32(const void* p) {
    uint32_t a;
    asm("{ .reg .u64 t; cvta.to.shared.u64 t, %1; cvt.u32.u64 %0, t; }" : "=r"(a) : "l"(p));
    return a;
}
__device__ __forceinline__ uint32_t sw64_(uint32_t off) { return off ^ ((off >> 3) & 0x30); }

__device__ __forceinline__ void ldsm_x4(uint32_t* r, uint32_t addr) {
    asm volatile("ldmatrix.sync.aligned.m8n8.x4.shared.b16 {%0,%1,%2,%3}, [%4];"
        : "=r"(r[0]), "=r"(r[1]), "=r"(r[2]), "=r"(r[3]) : "r"(addr));
}
__device__ __forceinline__ void mma_f16(float* c, const uint32_t* a, const uint32_t* b) {
    asm volatile("mma.sync.aligned.m16n8k16.row.col.f32.f16.f16.f32 "
        "{%0,%1,%2,%3}, {%4,%5,%6,%7}, {%8,%9}, {%0,%1,%2,%3};"
        : "+f"(c[0]), "+f"(c[1]), "+f"(c[2]), "+f"(c[3])
        : "r"(a[0]), "r"(a[1]), "r"(a[2]), "r"(a[3]), "r"(b[0]), "r"(b[1]));
}

// ---------------- clear (must precede prep's degree atomics) ----------------
__global__ void clear_kernel() {
    int i = blockIdx.x * blockDim.x + threadIdx.x;
    if (i < NN) {
        g_deg[i] = 0; g_cursor[i] = 0;
        g_as1[i] = 0.f; g_ad1[i] = 0.f;
        g_as2[i] = 0.f; g_ad2[i] = 0.f;
    }
}

// ---------------- fused prep: W1^T, W2^T, A->fp16, edge convert + degree ----------------
#define PREP_WT   576
#define PREP_A    432
#define PREP_EDGE 98
#define PREP_GRID (2 * PREP_WT + PREP_A + PREP_EDGE)   // 1682

__global__ __launch_bounds__(256) void prep_kernel(
    const float* __restrict__ W1, const float* __restrict__ W2,
    const float* __restrict__ x, const int* __restrict__ eraw)
{
    __shared__ float t[32][33];
    int b = blockIdx.x, tid = threadIdx.x;

    if (b < 2 * PREP_WT) {                     // ---- W transpose ----
        const float* W = (b < PREP_WT) ? W1 : W2;
        __half* Bt = (b < PREP_WT) ? g_b16a : g_b16b;
        int i = (b < PREP_WT) ? b : b - PREP_WT;
        int bx = (i % 24) * 32;                // n block
        int by = (i / 24) * 32;                // k block
        int tx = tid & 31;
        int ty = tid >> 5;
        #pragma unroll
        for (int j = 0; j < 32; j += 8)
            t[ty + j][tx] = W[(size_t)(by + ty + j) * DD + bx + tx];
        __syncthreads();
        #pragma unroll
        for (int j = 0; j < 32; j += 8)
            Bt[(size_t)(bx + ty + j) * DD + by + tx] = __float2half(t[tx][ty + j]);
    } else if (b < 2 * PREP_WT + PREP_A) {     // ---- A convert (float4 -> half2x2) ----
        const float4* x4 = (const float4*)x;
        uint2* a4 = (uint2*)g_af16;
        const int n4 = NN * DD / 4;
        const int p4 = NPAD * DD / 4;
        int idx = (b - 2 * PREP_WT) * 256 + tid;
        int stride = PREP_A * 256;
        for (int i = idx; i < p4; i += stride) {
            uint2 o;
            if (i < n4) {
                float4 v = x4[i];
                __half2 lo = __floats2half2_rn(v.x, v.y);
                __half2 hi = __floats2half2_rn(v.z, v.w);
                o.x = *(uint32_t*)&lo;
                o.y = *(uint32_t*)&hi;
            } else {
                o.x = 0u; o.y = 0u;
            }
            a4[i] = o;
        }
    } else {                                   // ---- edge convert + degree ----
        bool is64 = true;
        #pragma unroll
        for (int i = 1; i < 129; i += 2)
            if (eraw[i] != 0) is64 = false;
        int idx = (b - 2 * PREP_WT - PREP_A) * 256 + tid;
        int stride = PREP_EDGE * 256;
        for (int e = idx; e < 2 * NE; e += stride) {
            int v = is64 ? eraw[2 * e] : eraw[e];
            if (e < NE) g_src[e] = v;
            else { g_dst[e - NE] = v; atomicAdd(&g_deg[v], 1); }
        }
    }
}

// ---------------- CSR: scan (+1 self-loop per node) then scatter ----------------
__global__ __launch_bounds__(1024) void scan_kernel() {
    __shared__ int wsum[32];
    __shared__ int carry_s;
    int tid = threadIdx.x, lane = tid & 31, w = tid >> 5;
    if (tid == 0) { carry_s = 0; g_rowstart[0] = 0; }
    __syncthreads();
    for (int r = 0; r < 10; r++) {
        int i = r * 1024 + tid;
        int v = (i < NN) ? (g_deg[i] + 1) : 0;    // +1 = self-loop
        int ss = v;
        #pragma unroll
        for (int o = 1; o < 32; o <<= 1) {
            int tt = __shfl_up_sync(0xffffffffu, ss, o);
            if (lane >= o) ss += tt;
        }
        if (lane == 31) wsum[w] = ss;
        __syncthreads();
        if (w == 0) {
            int xx = wsum[lane];
            #pragma unroll
            for (int o = 1; o < 32; o <<= 1) {
                int tt = __shfl_up_sync(0xffffffffu, xx, o);
                if (lane >= o) xx += tt;
            }
            wsum[lane] = xx;
        }
        __syncthreads();
        int incl = ss + (w > 0 ? wsum[w - 1] : 0) + carry_s;
        if (i < NN) g_rowstart[i + 1] = incl;
        int total = carry_s + wsum[31];
        __syncthreads();
        if (tid == 0) carry_s = total;
        __syncthreads();
    }
}

__global__ void scatter_kernel() {
    int idx = blockIdx.x * blockDim.x + threadIdx.x;
    int stride = gridDim.x * blockDim.x;
    for (int e = idx; e < NE + NN; e += stride) {
        if (e < NE) {
            int s = g_src[e], d = g_dst[e];
            int pos = g_rowstart[d] + atomicAdd(&g_cursor[d], 1);
            g_csr_src[pos] = s;
        } else {
            int nd = e - NE;                       // self-loop at segment end
            g_csr_src[g_rowstart[nd + 1] - 1] = nd;
        }
    }
}

// ---------------- mma.sync fp16 GEMM + fused attn dots ----------------
#define BM 128
#define BN 128
#define BK 32
#define KCH (DD / BK)            // 24
#define TILE_B 8192              // 128 rows * 64 B
#define STAGE_B (2 * TILE_B)     // 16384
#define NSTAGE 4
#define GEMM_SMEM (NSTAGE * STAGE_B)  // 65536

__device__ __forceinline__ void gemm_issue_loads(
    uint32_t tiles_base, int buf, int kc, int tid, int row0, int col0,
    const __half* __restrict__ A, const __half* __restrict__ B)
{
    uint32_t base = tiles_base + (uint32_t)buf * STAGE_B;
    #pragma unroll
    for (int i = tid; i < 1024; i += 256) {
        int t = i >> 9;
        int j = i & 511;
        int r = j >> 2;
        int c16 = j & 3;
        const __half* src = (t == 0) ? A : B;
        int rowbase = (t == 0) ? row0 : col0;
        const void* g = src + (size_t)(rowbase + r) * DD + kc * BK + c16 * 8;
        uint32_t d = base + (uint32_t)t * TILE_B + sw64_((uint32_t)(r * 64 + c16 * 16));
        asm volatile("cp.async.cg.shared.global [%0], [%1], 16;\n" :: "r"(d), "l"(g) : "memory");
    }
    asm volatile("cp.async.commit_group;\n" ::: "memory");
}

__global__ __launch_bounds__(256, 2)
void gemm_f16_kernel(const __half* __restrict__ A,
                     const __half* __restrict__ B,
                     __half* __restrict__ C, int M,
                     const float* __restrict__ atts,
                     const float* __restrict__ attd,
                     float* __restrict__ as_, float* __restrict__ ad_)
{
    extern __shared__ char smem[];
    uint32_t sb = smem_u32(smem);
    int tid = threadIdx.x, wid = tid >> 5, lane = tid & 31;
    int row0 = blockIdx.y * BM;
    int col0 = blockIdx.x * BN;
    int warpM = wid & 3;
    int warpN = wid >> 2;

    float acc[2][8][4];
    #pragma unroll
    for (int mt = 0; mt < 2; mt++)
        #pragma unroll
        for (int nt = 0; nt < 8; nt++)
            #pragma unroll
            for (int q = 0; q < 4; q++) acc[mt][nt][q] = 0.f;

    int a_row_l = (lane & 7) + (((lane >> 3) & 1) << 3);
    int a_kb_l  = (lane >> 4) << 4;
    int b_row_l = (lane & 7) + ((lane >> 4) << 3);
    int b_kb_l  = ((lane >> 3) & 1) << 4;

    gemm_issue_loads(sb, 0, 0, tid, row0, col0, A, B);
    gemm_issue_loads(sb, 1, 1, tid, row0, col0, A, B);
    gemm_issue_loads(sb, 2, 2, tid, row0, col0, A, B);

    for (int c = 0; c < KCH; c++) {
        int rem = KCH - 1 - c;
        if (rem >= 2)      { asm volatile("cp.async.wait_group 2;\n" ::: "memory"); }
        else if (rem == 1) { asm volatile("cp.async.wait_group 1;\n" ::: "memory"); }
        else               { asm volatile("cp.async.wait_group 0;\n" ::: "memory"); }
        __syncthreads();
        if (c + 3 < KCH)
            gemm_issue_loads(sb, (c + 3) % NSTAGE, c + 3, tid, row0, col0, A, B);

        uint32_t sbase = sb + (uint32_t)(c % NSTAGE) * STAGE_B;
        uint32_t sA = sbase;
        uint32_t sB = sbase + TILE_B;

        #pragma unroll
        for (int ks = 0; ks < 2; ks++) {
            int kb = ks * 32;
            uint32_t ah[2][4];
            #pragma unroll
            for (int mt = 0; mt < 2; mt++) {
                int row = warpM * 32 + mt * 16 + a_row_l;
                uint32_t off = sw64_((uint32_t)(row * 64 + kb + a_kb_l));
                ldsm_x4(ah[mt], sA + off);
            }
            #pragma unroll
            for (int np = 0; np < 4; np++) {
                uint32_t bf[4];
                int nrow = warpN * 64 + np * 16 + b_row_l;
                uint32_t off = sw64_((uint32_t)(nrow * 64 + kb + b_kb_l));
                ldsm_x4(bf, sB + off);
                #pragma unroll
                for (int mt = 0; mt < 2; mt++) {
                    mma_f16(acc[mt][2 * np],     ah[mt], &bf[0]);
                    mma_f16(acc[mt][2 * np + 1], ah[mt], &bf[2]);
                }
            }
        }
    }

    int colb = col0 + warpN * 64 + (lane & 3) * 2;
    int rowb = row0 + warpM * 32 + (lane >> 2);

    // ---- fused attention dots (fp32 accumulators) ----
    {
        float ps[2][2] = {{0.f,0.f},{0.f,0.f}};
        float pd[2][2] = {{0.f,0.f},{0.f,0.f}};
        #pragma unroll
        for (int nt = 0; nt < 8; nt++) {
            int col = colb + nt * 8;
            float s0 = atts[col], s1 = atts[col + 1];
            float d0 = attd[col], d1 = attd[col + 1];
            #pragma unroll
            for (int mt = 0; mt < 2; mt++) {
                ps[mt][0] += acc[mt][nt][0] * s0 + acc[mt][nt][1] * s1;
                pd[mt][0] += acc[mt][nt][0] * d0 + acc[mt][nt][1] * d1;
                ps[mt][1] += acc[mt][nt][2] * s0 + acc[mt][nt][3] * s1;
                pd[mt][1] += acc[mt][nt][2] * d0 + acc[mt][nt][3] * d1;
            }
        }
        #pragma unroll
        for (int mt = 0; mt < 2; mt++)
            #pragma unroll
            for (int hf = 0; hf < 2; hf++) {
                #pragma unroll
                for (int o = 1; o < 4; o <<= 1) {
                    ps[mt][hf] += __shfl_xor_sync(0xffffffffu, ps[mt][hf], o);
                    pd[mt][hf] += __shfl_xor_sync(0xffffffffu, pd[mt][hf], o);
                }
            }
        if ((lane & 3) == 0) {
            #pragma unroll
            for (int mt = 0; mt < 2; mt++)
                #pragma unroll
                for (int hf = 0; hf < 2; hf++) {
                    int row = rowb + mt * 16 + hf * 8;
                    if (row < M) {
                        atomicAdd(&as_[row], ps[mt][hf]);
                        atomicAdd(&ad_[row], pd[mt][hf]);
                    }
                }
        }
    }

    // ---- store C as fp16 ----
    #pragma unroll
    for (int mt = 0; mt < 2; mt++) {
        int r0 = rowb + mt * 16;
        int r1 = r0 + 8;
        #pragma unroll
        for (int nt = 0; nt < 8; nt++) {
            int col = colb + nt * 8;
            if (r0 < M) *(__half2*)(C + (size_t)r0 * DD + col) =
                __floats2half2_rn(acc[mt][nt][0], acc[mt][nt][1]);
            if (r1 < M) *(__half2*)(C + (size_t)r1 * DD + col) =
                __floats2half2_rn(acc[mt][nt][2], acc[mt][nt][3]);
        }
    }
}

// ---------------- segment softmax + weighted aggregate ----------------
#define AGG_T 384
__global__ __launch_bounds__(AGG_T) void aggregate_kernel(
    const __half* __restrict__ h, const float* __restrict__ bias,
    const float* __restrict__ as_, const float* __restrict__ ad_,
    float* __restrict__ out, int mode)
{
    __shared__ float sh_alpha[AGG_T];
    __shared__ int   sh_src[AGG_T];
    __shared__ float red[12];
    __shared__ float s_b;

    int n = blockIdx.x, tid = threadIdx.x;
    int lane = tid & 31, w = tid >> 5;
    int rs = g_rowstart[n], re = g_rowstart[n + 1];
    float adn = ad_[n];

    float2 acc = make_float2(0.f, 0.f);
    float total = 0.f;

    for (int base = rs; base < re; base += AGG_T) {
        int cnt = min(AGG_T, re - base);
        float ex = 0.f; int s = 0;
        if (tid < cnt) {
            s = g_csr_src[base + tid];
            float t = as_[s] + adn;
            t = (t > 0.f) ? t : NEG_SLOPE * t;
            ex = __expf(t);
        }
        float v = ex;
        #pragma unroll
        for (int o = 16; o > 0; o >>= 1)
            v += __shfl_xor_sync(0xffffffffu, v, o);
        if (lane == 0) red[w] = v;
        if (tid < cnt) { sh_alpha[tid] = ex; sh_src[tid] = s; }
        __syncthreads();
        if (tid == 0) {
            float ss = 0.f;
            #pragma unroll
            for (int q = 0; q < 12; q++) ss += red[q];
            s_b = ss;
        }
        __syncthreads();
        total += s_b;

        #pragma unroll 4
        for (int j = 0; j < cnt; j++) {
            float a = sh_alpha[j];
            const __half2* hr = (const __half2*)(h + (size_t)sh_src[j] * DD);
            float2 f = __half22float2(hr[tid]);
            acc.x = fmaf(a, f.x, acc.x);
            acc.y = fmaf(a, f.y, acc.y);
        }
        __syncthreads();
    }

    float inv = 1.f / total;
    int c0 = 2 * tid;
    float2 bv = *(const float2*)(bias + c0);
    float o0 = acc.x * inv + bv.x;
    float o1 = acc.y * inv + bv.y;
    if (mode == 1) {
        o0 = fmaxf(o0, 0.f); o1 = fmaxf(o1, 0.f);
        *(__half2*)(&g_af16[(size_t)n * DD + c0]) = __floats2half2_rn(o0, o1);
    } else {
        *(float2*)(out + (size_t)n * DD + c0) = make_float2(o0, o1);
    }
}

// ---------------- launch ----------------
extern "C" void kernel_launch(void* const* d_in, const int* in_sizes, int n_in,
                              void* d_out, int out_size) {
    const float* x   = (const float*)d_in[0];
    const int*   er  = (const int*)d_in[1];
    const float* W1  = (const float*)d_in[2];
    const float* as1 = (const float*)d_in[3];
    const float* ad1 = (const float*)d_in[4];
    const float* b1  = (const float*)d_in[5];
    const float* W2  = (const float*)d_in[6];
    const float* as2 = (const float*)d_in[7];
    const float* ad2 = (const float*)d_in[8];
    const float* b2  = (const float*)d_in[9];
    float* out = (float*)d_out;

    void *p_h, *p_a, *p_ba, *p_bb, *p_s1, *p_d1, *p_s2, *p_d2;
    cudaGetSymbolAddress(&p_h, g_h);
    cudaGetSymbolAddress(&p_a, g_af16);
    cudaGetSymbolAddress(&p_ba, g_b16a);
    cudaGetSymbolAddress(&p_bb, g_b16b);
    cudaGetSymbolAddress(&p_s1, g_as1);
    cudaGetSymbolAddress(&p_d1, g_ad1);
    cudaGetSymbolAddress(&p_s2, g_as2);
    cudaGetSymbolAddress(&p_d2, g_ad2);
    __half* h = (__half*)p_h;
    const __half* a16 = (const __half*)p_a;

    cudaFuncSetAttribute(gemm_f16_kernel,
                         cudaFuncAttributeMaxDynamicSharedMemorySize, GEMM_SMEM);

    // side stream + fork/join events (created once; no device memory involved)
    static cudaStream_t s_csr = nullptr;
    static cudaEvent_t ev_prep = nullptr, ev_csr = nullptr;
    if (s_csr == nullptr) {
        cudaStreamCreateWithFlags(&s_csr, cudaStreamNonBlocking);
        cudaEventCreateWithFlags(&ev_prep, cudaEventDisableTiming);
        cudaEventCreateWithFlags(&ev_csr, cudaEventDisableTiming);
    }

    dim3 ggrid(DD / BN, NPAD / BM);          // (6, 79)

    // main: clear -> prep -> gemm1 -> (join csr) agg1 -> gemm2 -> agg2
    // csr : (fork after prep) scan -> scatter   (hides under gemm1)
    clear_kernel<<<(NN + 255) / 256, 256>>>();
    prep_kernel<<<PREP_GRID, 256>>>(W1, W2, x, er);
    cudaEventRecord(ev_prep, 0);
    cudaStreamWaitEvent(s_csr, ev_prep, 0);
    scan_kernel<<<1, 1024, 0, s_csr>>>();
    scatter_kernel<<<432, 256, 0, s_csr>>>();
    cudaEventRecord(ev_csr, s_csr);

    gemm_f16_kernel<<<ggrid, 256, GEMM_SMEM>>>(a16, (const __half*)p_ba,
        h, NN, as1, ad1, (float*)p_s1, (float*)p_d1);

    cudaStreamWaitEvent(0, ev_csr, 0);
    aggregate_kernel<<<NN, AGG_T>>>(h, b1, (const float*)p_s1,
        (const float*)p_d1, nullptr, 1);
    gemm_f16_kernel<<<ggrid, 256, GEMM_SMEM>>>(a16, (const __half*)p_bb,
        h, NN, as2, ad2, (float*)p_s2, (float*)p_d2);
    aggregate_kernel<<<NN, AGG_T>>>(h, b2, (const float*)p_s2,
        (const float*)p_d2, out, 0);
}

// round 17
// speedup vs baseline: 1.6214x; 1.0923x over previous
#include <cuda_runtime.h>
#include <cuda_bf16.h>
#include <cuda_fp16.h>
#include <math.h>
#include <stdint.h>

#define NN 10000
#define NPAD 10112        // 79 * 128
#define NE 100000
#define NEP 110000        // edges + self-loops
#define DD 768
#define NEG_SLOPE 0.2f

// ---------------- scratch (device globals; no allocation allowed) ----------------
__device__ __half g_h[NN * DD];        // GEMM output, fp16
__device__ float g_as1[NN];
__device__ float g_ad1[NN];
__device__ float g_as2[NN];
__device__ float g_ad2[NN];
__device__ int   g_src[NE];
__device__ int   g_dst[NE];
__device__ int   g_deg[NN];            // real-edge in-degree (self-loop added in scan)
__device__ int   g_rowstart[NN + 1];
__device__ int   g_cursor[NN];
__device__ int   g_csr_src[NEP];
__device__ __half g_af16[NPAD * DD];   // A in fp16
__device__ __half g_b16a[DD * DD];     // W1^T fp16 [n][k]
__device__ __half g_b16b[DD * DD];     // W2^T fp16 [n][k]

// ================= helpers =================
__device__ __forceinline__ uint32_t smem_u32(const void* p) {
    uint32_t a;
    asm("{ .reg .u64 t; cvta.to.shared.u64 t, %1; cvt.u32.u64 %0, t; }" : "=r"(a) : "l"(p));
    return a;
}
__device__ __forceinline__ uint32_t sw64_(uint32_t off) { return off ^ ((off >> 3) & 0x30); }

__device__ __forceinline__ void ldsm_x4(uint32_t* r, uint32_t addr) {
    asm volatile("ldmatrix.sync.aligned.m8n8.x4.shared.b16 {%0,%1,%2,%3}, [%4];"
        : "=r"(r[0]), "=r"(r[1]), "=r"(r[2]), "=r"(r[3]) : "r"(addr));
}
__device__ __forceinline__ void mma_f16(float* c, const uint32_t* a, const uint32_t* b) {
    asm volatile("mma.sync.aligned.m16n8k16.row.col.f32.f16.f16.f32 "
        "{%0,%1,%2,%3}, {%4,%5,%6,%7}, {%8,%9}, {%0,%1,%2,%3};"
        : "+f"(c[0]), "+f"(c[1]), "+f"(c[2]), "+f"(c[3])
        : "r"(a[0]), "r"(a[1]), "r"(a[2]), "r"(a[3]), "r"(b[0]), "r"(b[1]));
}

// ---------------- clear (must precede prep's degree atomics) ----------------
__global__ void clear_kernel() {
    int i = blockIdx.x * blockDim.x + threadIdx.x;
    if (i < NN) {
        g_deg[i] = 0; g_cursor[i] = 0;
        g_as1[i] = 0.f; g_ad1[i] = 0.f;
        g_as2[i] = 0.f; g_ad2[i] = 0.f;
    }
}

// ---------------- fused prep: W1^T, W2^T, A->fp16, edge convert + degree ----------------
#define PREP_WT   576
#define PREP_A    432
#define PREP_EDGE 98
#define PREP_GRID (2 * PREP_WT + PREP_A + PREP_EDGE)   // 1682

__global__ __launch_bounds__(256) void prep_kernel(
    const float* __restrict__ W1, const float* __restrict__ W2,
    const float* __restrict__ x, const int* __restrict__ eraw)
{
    __shared__ float t[32][33];
    int b = blockIdx.x, tid = threadIdx.x;

    if (b < 2 * PREP_WT) {                     // ---- W transpose ----
        const float* W = (b < PREP_WT) ? W1 : W2;
        __half* Bt = (b < PREP_WT) ? g_b16a : g_b16b;
        int i = (b < PREP_WT) ? b : b - PREP_WT;
        int bx = (i % 24) * 32;                // n block
        int by = (i / 24) * 32;                // k block
        int tx = tid & 31;
        int ty = tid >> 5;
        #pragma unroll
        for (int j = 0; j < 32; j += 8)
            t[ty + j][tx] = W[(size_t)(by + ty + j) * DD + bx + tx];
        __syncthreads();
        #pragma unroll
        for (int j = 0; j < 32; j += 8)
            Bt[(size_t)(bx + ty + j) * DD + by + tx] = __float2half(t[tx][ty + j]);
    } else if (b < 2 * PREP_WT + PREP_A) {     // ---- A convert (float4 -> half2x2) ----
        const float4* x4 = (const float4*)x;
        uint2* a4 = (uint2*)g_af16;
        const int n4 = NN * DD / 4;
        const int p4 = NPAD * DD / 4;
        int idx = (b - 2 * PREP_WT) * 256 + tid;
        int stride = PREP_A * 256;
        for (int i = idx; i < p4; i += stride) {
            uint2 o;
            if (i < n4) {
                float4 v = x4[i];
                __half2 lo = __floats2half2_rn(v.x, v.y);
                __half2 hi = __floats2half2_rn(v.z, v.w);
                o.x = *(uint32_t*)&lo;
                o.y = *(uint32_t*)&hi;
            } else {
                o.x = 0u; o.y = 0u;
            }
            a4[i] = o;
        }
    } else {                                   // ---- edge convert + degree ----
        bool is64 = true;
        #pragma unroll
        for (int i = 1; i < 129; i += 2)
            if (eraw[i] != 0) is64 = false;
        int idx = (b - 2 * PREP_WT - PREP_A) * 256 + tid;
        int stride = PREP_EDGE * 256;
        for (int e = idx; e < 2 * NE; e += stride) {
            int v = is64 ? eraw[2 * e] : eraw[e];
            if (e < NE) g_src[e] = v;
            else { g_dst[e - NE] = v; atomicAdd(&g_deg[v], 1); }
        }
    }
}

// ---------------- CSR: scan (+1 self-loop per node) then scatter ----------------
__global__ __launch_bounds__(1024) void scan_kernel() {
    __shared__ int wsum[32];
    __shared__ int carry_s;
    int tid = threadIdx.x, lane = tid & 31, w = tid >> 5;
    if (tid == 0) { carry_s = 0; g_rowstart[0] = 0; }
    __syncthreads();
    for (int r = 0; r < 10; r++) {
        int i = r * 1024 + tid;
        int v = (i < NN) ? (g_deg[i] + 1) : 0;    // +1 = self-loop
        int ss = v;
        #pragma unroll
        for (int o = 1; o < 32; o <<= 1) {
            int tt = __shfl_up_sync(0xffffffffu, ss, o);
            if (lane >= o) ss += tt;
        }
        if (lane == 31) wsum[w] = ss;
        __syncthreads();
        if (w == 0) {
            int xx = wsum[lane];
            #pragma unroll
            for (int o = 1; o < 32; o <<= 1) {
                int tt = __shfl_up_sync(0xffffffffu, xx, o);
                if (lane >= o) xx += tt;
            }
            wsum[lane] = xx;
        }
        __syncthreads();
        int incl = ss + (w > 0 ? wsum[w - 1] : 0) + carry_s;
        if (i < NN) g_rowstart[i + 1] = incl;
        int total = carry_s + wsum[31];
        __syncthreads();
        if (tid == 0) carry_s = total;
        __syncthreads();
    }
}

__global__ void scatter_kernel() {
    int idx = blockIdx.x * blockDim.x + threadIdx.x;
    int stride = gridDim.x * blockDim.x;
    for (int e = idx; e < NE + NN; e += stride) {
        if (e < NE) {
            int s = g_src[e], d = g_dst[e];
            int pos = g_rowstart[d] + atomicAdd(&g_cursor[d], 1);
            g_csr_src[pos] = s;
        } else {
            int nd = e - NE;                       // self-loop at segment end
            g_csr_src[g_rowstart[nd + 1] - 1] = nd;
        }
    }
}

// ---------------- mma.sync fp16 GEMM + fused attn dots ----------------
// CTA tile 128x64, warp tile 32x32 (8 warps 4Mx2N), 3 CTAs/SM target.
#define BM 128
#define BN 64
#define BK 32
#define KCH (DD / BK)            // 24
#define TILE_A_B 8192            // 128 rows * 64 B
#define TILE_B_B 4096            // 64 rows * 64 B
#define STAGE_B (TILE_A_B + TILE_B_B)   // 12288
#define NSTAGE 4
#define GEMM_SMEM (NSTAGE * STAGE_B)    // 49152

__device__ __forceinline__ void gemm_issue_loads(
    uint32_t tiles_base, int buf, int kc, int tid, int row0, int col0,
    const __half* __restrict__ A, const __half* __restrict__ B)
{
    uint32_t base = tiles_base + (uint32_t)buf * STAGE_B;
    // 768 16B-units per stage: 512 for A (128 rows x 4), 256 for B (64 rows x 4)
    #pragma unroll
    for (int i = tid; i < 768; i += 256) {
        int isB = (i >= 512);
        int j = isB ? (i - 512) : i;
        int r = j >> 2;
        int c16 = j & 3;
        const __half* src = isB ? B : A;
        int rowbase = isB ? col0 : row0;
        uint32_t toff = isB ? TILE_A_B : 0u;
        const void* g = src + (size_t)(rowbase + r) * DD + kc * BK + c16 * 8;
        uint32_t d = base + toff + sw64_((uint32_t)(r * 64 + c16 * 16));
        asm volatile("cp.async.cg.shared.global [%0], [%1], 16;\n" :: "r"(d), "l"(g) : "memory");
    }
    asm volatile("cp.async.commit_group;\n" ::: "memory");
}

__global__ __launch_bounds__(256, 3)
void gemm_f16_kernel(const __half* __restrict__ A,
                     const __half* __restrict__ B,
                     __half* __restrict__ C, int M,
                     const float* __restrict__ atts,
                     const float* __restrict__ attd,
                     float* __restrict__ as_, float* __restrict__ ad_)
{
    extern __shared__ char smem[];
    uint32_t sb = smem_u32(smem);
    int tid = threadIdx.x, wid = tid >> 5, lane = tid & 31;
    int row0 = blockIdx.y * BM;
    int col0 = blockIdx.x * BN;
    int warpM = wid & 3;        // 0..3 -> 32-row slice
    int warpN = wid >> 2;       // 0..1 -> 32-col slice

    float acc[2][4][4];
    #pragma unroll
    for (int mt = 0; mt < 2; mt++)
        #pragma unroll
        for (int nt = 0; nt < 4; nt++)
            #pragma unroll
            for (int q = 0; q < 4; q++) acc[mt][nt][q] = 0.f;

    int a_row_l = (lane & 7) + (((lane >> 3) & 1) << 3);
    int a_kb_l  = (lane >> 4) << 4;
    int b_row_l = (lane & 7) + ((lane >> 4) << 3);
    int b_kb_l  = ((lane >> 3) & 1) << 4;

    gemm_issue_loads(sb, 0, 0, tid, row0, col0, A, B);
    gemm_issue_loads(sb, 1, 1, tid, row0, col0, A, B);
    gemm_issue_loads(sb, 2, 2, tid, row0, col0, A, B);

    for (int c = 0; c < KCH; c++) {
        int rem = KCH - 1 - c;
        if (rem >= 2)      { asm volatile("cp.async.wait_group 2;\n" ::: "memory"); }
        else if (rem == 1) { asm volatile("cp.async.wait_group 1;\n" ::: "memory"); }
        else               { asm volatile("cp.async.wait_group 0;\n" ::: "memory"); }
        __syncthreads();
        if (c + 3 < KCH)
            gemm_issue_loads(sb, (c + 3) % NSTAGE, c + 3, tid, row0, col0, A, B);

        uint32_t sbase = sb + (uint32_t)(c % NSTAGE) * STAGE_B;
        uint32_t sA = sbase;
        uint32_t sB = sbase + TILE_A_B;

        #pragma unroll
        for (int ks = 0; ks < 2; ks++) {
            int kb = ks * 32;
            uint32_t ah[2][4];
            #pragma unroll
            for (int mt = 0; mt < 2; mt++) {
                int row = warpM * 32 + mt * 16 + a_row_l;
                uint32_t off = sw64_((uint32_t)(row * 64 + kb + a_kb_l));
                ldsm_x4(ah[mt], sA + off);
            }
            #pragma unroll
            for (int np = 0; np < 2; np++) {
                uint32_t bf[4];
                int nrow = warpN * 32 + np * 16 + b_row_l;
                uint32_t off = sw64_((uint32_t)(nrow * 64 + kb + b_kb_l));
                ldsm_x4(bf, sB + off);
                #pragma unroll
                for (int mt = 0; mt < 2; mt++) {
                    mma_f16(acc[mt][2 * np],     ah[mt], &bf[0]);
                    mma_f16(acc[mt][2 * np + 1], ah[mt], &bf[2]);
                }
            }
        }
    }

    int colb = col0 + warpN * 32 + (lane & 3) * 2;
    int rowb = row0 + warpM * 32 + (lane >> 2);

    // ---- fused attention dots (fp32 accumulators) ----
    {
        float ps[2][2] = {{0.f,0.f},{0.f,0.f}};
        float pd[2][2] = {{0.f,0.f},{0.f,0.f}};
        #pragma unroll
        for (int nt = 0; nt < 4; nt++) {
            int col = colb + nt * 8;
            float s0 = atts[col], s1 = atts[col + 1];
            float d0 = attd[col], d1 = attd[col + 1];
            #pragma unroll
            for (int mt = 0; mt < 2; mt++) {
                ps[mt][0] += acc[mt][nt][0] * s0 + acc[mt][nt][1] * s1;
                pd[mt][0] += acc[mt][nt][0] * d0 + acc[mt][nt][1] * d1;
                ps[mt][1] += acc[mt][nt][2] * s0 + acc[mt][nt][3] * s1;
                pd[mt][1] += acc[mt][nt][2] * d0 + acc[mt][nt][3] * d1;
            }
        }
        #pragma unroll
        for (int mt = 0; mt < 2; mt++)
            #pragma unroll
            for (int hf = 0; hf < 2; hf++) {
                #pragma unroll
                for (int o = 1; o < 4; o <<= 1) {
                    ps[mt][hf] += __shfl_xor_sync(0xffffffffu, ps[mt][hf], o);
                    pd[mt][hf] += __shfl_xor_sync(0xffffffffu, pd[mt][hf], o);
                }
            }
        if ((lane & 3) == 0) {
            #pragma unroll
            for (int mt = 0; mt < 2; mt++)
                #pragma unroll
                for (int hf = 0; hf < 2; hf++) {
                    int row = rowb + mt * 16 + hf * 8;
                    if (row < M) {
                        atomicAdd(&as_[row], ps[mt][hf]);
                        atomicAdd(&ad_[row], pd[mt][hf]);
                    }
                }
        }
    }

    // ---- store C as fp16 ----
    #pragma unroll
    for (int mt = 0; mt < 2; mt++) {
        int r0 = rowb + mt * 16;
        int r1 = r0 + 8;
        #pragma unroll
        for (int nt = 0; nt < 4; nt++) {
            int col = colb + nt * 8;
            if (r0 < M) *(__half2*)(C + (size_t)r0 * DD + col) =
                __floats2half2_rn(acc[mt][nt][0], acc[mt][nt][1]);
            if (r1 < M) *(__half2*)(C + (size_t)r1 * DD + col) =
                __floats2half2_rn(acc[mt][nt][2], acc[mt][nt][3]);
        }
    }
}

// ---------------- segment softmax + weighted aggregate ----------------
#define AGG_T 384
__global__ __launch_bounds__(AGG_T) void aggregate_kernel(
    const __half* __restrict__ h, const float* __restrict__ bias,
    const float* __restrict__ as_, const float* __restrict__ ad_,
    float* __restrict__ out, int mode)
{
    __shared__ float sh_alpha[AGG_T];
    __shared__ int   sh_src[AGG_T];
    __shared__ float red[12];
    __shared__ float s_b;

    int n = blockIdx.x, tid = threadIdx.x;
    int lane = tid & 31, w = tid >> 5;
    int rs = g_rowstart[n], re = g_rowstart[n + 1];
    float adn = ad_[n];

    float2 acc = make_float2(0.f, 0.f);
    float total = 0.f;

    for (int base = rs; base < re; base += AGG_T) {
        int cnt = min(AGG_T, re - base);
        float ex = 0.f; int s = 0;
        if (tid < cnt) {
            s = g_csr_src[base + tid];
            float t = as_[s] + adn;
            t = (t > 0.f) ? t : NEG_SLOPE * t;
            ex = __expf(t);
        }
        float v = ex;
        #pragma unroll
        for (int o = 16; o > 0; o >>= 1)
            v += __shfl_xor_sync(0xffffffffu, v, o);
        if (lane == 0) red[w] = v;
        if (tid < cnt) { sh_alpha[tid] = ex; sh_src[tid] = s; }
        __syncthreads();
        if (tid == 0) {
            float ss = 0.f;
            #pragma unroll
            for (int q = 0; q < 12; q++) ss += red[q];
            s_b = ss;
        }
        __syncthreads();
        total += s_b;

        #pragma unroll 4
        for (int j = 0; j < cnt; j++) {
            float a = sh_alpha[j];
            const __half2* hr = (const __half2*)(h + (size_t)sh_src[j] * DD);
            float2 f = __half22float2(hr[tid]);
            acc.x = fmaf(a, f.x, acc.x);
            acc.y = fmaf(a, f.y, acc.y);
        }
        __syncthreads();
    }

    float inv = 1.f / total;
    int c0 = 2 * tid;
    float2 bv = *(const float2*)(bias + c0);
    float o0 = acc.x * inv + bv.x;
    float o1 = acc.y * inv + bv.y;
    if (mode == 1) {
        o0 = fmaxf(o0, 0.f); o1 = fmaxf(o1, 0.f);
        *(__half2*)(&g_af16[(size_t)n * DD + c0]) = __floats2half2_rn(o0, o1);
    } else {
        *(float2*)(out + (size_t)n * DD + c0) = make_float2(o0, o1);
    }
}

// ---------------- launch ----------------
extern "C" void kernel_launch(void* const* d_in, const int* in_sizes, int n_in,
                              void* d_out, int out_size) {
    const float* x   = (const float*)d_in[0];
    const int*   er  = (const int*)d_in[1];
    const float* W1  = (const float*)d_in[2];
    const float* as1 = (const float*)d_in[3];
    const float* ad1 = (const float*)d_in[4];
    const float* b1  = (const float*)d_in[5];
    const float* W2  = (const float*)d_in[6];
    const float* as2 = (const float*)d_in[7];
    const float* ad2 = (const float*)d_in[8];
    const float* b2  = (const float*)d_in[9];
    float* out = (float*)d_out;

    void *p_h, *p_a, *p_ba, *p_bb, *p_s1, *p_d1, *p_s2, *p_d2;
    cudaGetSymbolAddress(&p_h, g_h);
    cudaGetSymbolAddress(&p_a, g_af16);
    cudaGetSymbolAddress(&p_ba, g_b16a);
    cudaGetSymbolAddress(&p_bb, g_b16b);
    cudaGetSymbolAddress(&p_s1, g_as1);
    cudaGetSymbolAddress(&p_d1, g_ad1);
    cudaGetSymbolAddress(&p_s2, g_as2);
    cudaGetSymbolAddress(&p_d2, g_ad2);
    __half* h = (__half*)p_h;
    const __half* a16 = (const __half*)p_a;

    cudaFuncSetAttribute(gemm_f16_kernel,
                         cudaFuncAttributeMaxDynamicSharedMemorySize, GEMM_SMEM);

    // side stream + fork/join events (created once; no device memory involved)
    static cudaStream_t s_csr = nullptr;
    static cudaEvent_t ev_prep = nullptr, ev_csr = nullptr;
    if (s_csr == nullptr) {
        cudaStreamCreateWithFlags(&s_csr, cudaStreamNonBlocking);
        cudaEventCreateWithFlags(&ev_prep, cudaEventDisableTiming);
        cudaEventCreateWithFlags(&ev_csr, cudaEventDisableTiming);
    }

    dim3 ggrid(DD / BN, NPAD / BM);          // (12, 79)

    // main: clear -> prep -> gemm1 -> (join csr) agg1 -> gemm2 -> agg2
    // csr : (fork after prep) scan -> scatter   (hides under gemm1)
    clear_kernel<<<(NN + 255) / 256, 256>>>();
    prep_kernel<<<PREP_GRID, 256>>>(W1, W2, x, er);
    cudaEventRecord(ev_prep, 0);
    cudaStreamWaitEvent(s_csr, ev_prep, 0);
    scan_kernel<<<1, 1024, 0, s_csr>>>();
    scatter_kernel<<<432, 256, 0, s_csr>>>();
    cudaEventRecord(ev_csr, s_csr);

    gemm_f16_kernel<<<ggrid, 256, GEMM_SMEM>>>(a16, (const __half*)p_ba,
        h, NN, as1, ad1, (float*)p_s1, (float*)p_d1);

    cudaStreamWaitEvent(0, ev_csr, 0);
    aggregate_kernel<<<NN, AGG_T>>>(h, b1, (const float*)p_s1,
        (const float*)p_d1, nullptr, 1);
    gemm_f16_kernel<<<ggrid, 256, GEMM_SMEM>>>(a16, (const __half*)p_bb,
        h, NN, as2, ad2, (float*)p_s2, (float*)p_d2);
    aggregate_kernel<<<NN, AGG_T>>>(h, b2, (const float*)p_s2,
        (const float*)p_d2, out, 0);
}